// round 7
// baseline (speedup 1.0000x reference)
#include <cuda_runtime.h>
#include <math.h>
#include <stdint.h>

// Problem dims (fixed per metadata)
#define B_  16
#define P_  1000
#define N_  1000
#define E_  256
#define HD_ 256
#define H_  16
#define D_  16

// ---------------- scratch (no allocations allowed) ----------------
__device__ float g_K [B_ * N_ * HD_];
__device__ float g_V [B_ * N_ * HD_];
__device__ float g_Q [B_ * P_ * HD_];
__device__ float g_OC[B_ * P_ * HD_];
__device__ float g_MH[B_ * P_ * E_ ];
__device__ float g_S [(size_t)B_ * P_ * N_];   // 64 MB score scratch

// ================= 128x128x16 fp32 GEMM, 8x8 microtile =================
// B fragment is SPLIT: cols [tx*4, tx*4+4) and [64+tx*4, ...) -> per LDS.128
// phase the 8 lanes cover all 32 banks (conflict-free). A fragment reads are
// warp-broadcast (2 addresses). Per k-step: 4 LDS.128 feed 64 FFMA.
#define GM 128
#define GN 128
#define GK 16

__global__ void __launch_bounds__(256)
gemm128(const float* __restrict__ A, const float* __restrict__ Bw,
        float* __restrict__ C, int Nc,
        const float* __restrict__ bias,
        const float* __restrict__ attr,
        const float* __restrict__ attr_row)
{
    __shared__ float As[GK][GM + 4];
    __shared__ float Bs[GK][GN];
    const int Kdim = 256;
    int tid = threadIdx.x;
    int tx = tid & 15, ty = tid >> 4;
    int m0 = blockIdx.y * GM;
    int n0 = blockIdx.x * GN;

    int ar  = tid >> 1;            // 0..127  (A row within tile)
    int akq = (tid & 1) * 8;       // 0 or 8  (A k offset)
    int bk  = tid >> 4;            // 0..15   (B k row)
    int bc  = (tid & 15) * 8;      // B col offset (staging only)

    float acc[8][8] = {};          // acc[i][j]: j<4 -> col tx*4+j ; j>=4 -> col 64+tx*4+(j-4)

    for (int k0 = 0; k0 < Kdim; k0 += GK) {
        {   // A tile: 128 rows x 16 k, stored transposed
            const float* Ap = A + (size_t)(m0 + ar) * Kdim + k0 + akq;
            float4 a0 = *(const float4*)(Ap);
            float4 a1 = *(const float4*)(Ap + 4);
            As[akq + 0][ar] = a0.x; As[akq + 1][ar] = a0.y;
            As[akq + 2][ar] = a0.z; As[akq + 3][ar] = a0.w;
            As[akq + 4][ar] = a1.x; As[akq + 5][ar] = a1.y;
            As[akq + 6][ar] = a1.z; As[akq + 7][ar] = a1.w;
        }
        {   // B tile: 16 k x 128 n, contiguous
            const float* Bp = Bw + (size_t)(k0 + bk) * Nc + n0 + bc;
            *(float4*)(&Bs[bk][bc])     = *(const float4*)(Bp);
            *(float4*)(&Bs[bk][bc + 4]) = *(const float4*)(Bp + 4);
        }
        __syncthreads();
#pragma unroll
        for (int k = 0; k < GK; k++) {
            float a[8], b[8];
            *(float4*)(a)     = *(const float4*)(&As[k][ty * 8]);
            *(float4*)(a + 4) = *(const float4*)(&As[k][ty * 8 + 4]);
            *(float4*)(b)     = *(const float4*)(&Bs[k][tx * 4]);
            *(float4*)(b + 4) = *(const float4*)(&Bs[k][64 + tx * 4]);
#pragma unroll
            for (int i = 0; i < 8; i++)
#pragma unroll
                for (int j = 0; j < 8; j++)
                    acc[i][j] = fmaf(a[i], b[j], acc[i][j]);
        }
        __syncthreads();
    }

#pragma unroll
    for (int i = 0; i < 8; i++) {
        int m = m0 + ty * 8 + i;
        float am = attr ? attr[m] : 0.f;
        float* Cp = C + (size_t)m * Nc + n0;
#pragma unroll
        for (int half = 0; half < 2; half++) {
            int cbase = half * 64 + tx * 4;
            float4 v;
            float* vv = (float*)&v;
#pragma unroll
            for (int j = 0; j < 4; j++) {
                int n = n0 + cbase + j;
                float x = acc[i][half * 4 + j];
                if (bias) x += bias[n];
                if (attr) x += am * attr_row[n];
                vv[j] = x;
            }
            *(float4*)(Cp + cbase) = v;
        }
    }
}

// ======= probe score GEMM (A·B^T), 128x128 tile, 8x8 microtile, fused epilogue =======
// S[b] = 10*tanh((MH[b] @ enc[b]^T)/16) + mask[b];  M=P_, N=N_, K=256.
__global__ void __launch_bounds__(256)
abT128(const float* __restrict__ MH, const float* __restrict__ enc,
       const float* __restrict__ mask, float* __restrict__ S)
{
    __shared__ float As[GK][GM + 4];
    __shared__ float Bs[GK][GN + 4];
    const int Kdim = 256;
    int b   = blockIdx.z;
    int tid = threadIdx.x;
    int tx = tid & 15, ty = tid >> 4;
    int m0 = blockIdx.y * GM;
    int n0 = blockIdx.x * GN;

    const float* A  = MH  + (size_t)b * P_ * E_;
    const float* Bm = enc + (size_t)b * N_ * E_;

    int ar  = tid >> 1;
    int akq = (tid & 1) * 8;

    float acc[8][8] = {};

    for (int k0 = 0; k0 < Kdim; k0 += GK) {
        {   // A tile (row clamp for 1000 = 7*128 + 104 tail)
            int m = m0 + ar; if (m >= P_) m = P_ - 1;
            const float* Ap = A + (size_t)m * Kdim + k0 + akq;
            float4 a0 = *(const float4*)(Ap);
            float4 a1 = *(const float4*)(Ap + 4);
            As[akq + 0][ar] = a0.x; As[akq + 1][ar] = a0.y;
            As[akq + 2][ar] = a0.z; As[akq + 3][ar] = a0.w;
            As[akq + 4][ar] = a1.x; As[akq + 5][ar] = a1.y;
            As[akq + 6][ar] = a1.z; As[akq + 7][ar] = a1.w;
        }
        {   // B tile: rows are n-dim, transposed staging (row clamp)
            int n = n0 + ar; if (n >= N_) n = N_ - 1;
            const float* Bp = Bm + (size_t)n * Kdim + k0 + akq;
            float4 b0 = *(const float4*)(Bp);
            float4 b1 = *(const float4*)(Bp + 4);
            Bs[akq + 0][ar] = b0.x; Bs[akq + 1][ar] = b0.y;
            Bs[akq + 2][ar] = b0.z; Bs[akq + 3][ar] = b0.w;
            Bs[akq + 4][ar] = b1.x; Bs[akq + 5][ar] = b1.y;
            Bs[akq + 6][ar] = b1.z; Bs[akq + 7][ar] = b1.w;
        }
        __syncthreads();
#pragma unroll
        for (int k = 0; k < GK; k++) {
            float a[8], bb[8];
            *(float4*)(a)      = *(const float4*)(&As[k][ty * 8]);
            *(float4*)(a + 4)  = *(const float4*)(&As[k][ty * 8 + 4]);
            *(float4*)(bb)     = *(const float4*)(&Bs[k][tx * 4]);
            *(float4*)(bb + 4) = *(const float4*)(&Bs[k][64 + tx * 4]);
#pragma unroll
            for (int i = 0; i < 8; i++)
#pragma unroll
                for (int j = 0; j < 8; j++)
                    acc[i][j] = fmaf(a[i], bb[j], acc[i][j]);
        }
        __syncthreads();
    }

#pragma unroll
    for (int i = 0; i < 8; i++) {
        int m = m0 + ty * 8 + i;
        if (m >= P_) continue;
#pragma unroll
        for (int half = 0; half < 2; half++) {
#pragma unroll
            for (int j = 0; j < 4; j++) {
                int n = n0 + half * 64 + tx * 4 + j;
                if (n >= N_) continue;
                size_t idx = ((size_t)b * P_ + m) * N_ + n;
                S[idx] = 10.f * tanhf(acc[i][half * 4 + j] * 0.0625f) + mask[idx];
            }
        }
    }
}

// ---------------- fused multi-head attention (flash style, 2 p-rows / thread) ----------------
#define ACH 16

__global__ void __launch_bounds__(256)
attn_k(const float* __restrict__ Q, const float* __restrict__ K,
       const float* __restrict__ V, const float* __restrict__ mask,
       float* __restrict__ OC)
{
    extern __shared__ float sm[];
    float* k_sm = sm;                          // ACH * 256
    float* v_sm = k_sm + ACH * HD_;            // ACH * 256
    float* m_sm = v_sm + ACH * HD_;            // 32 * (ACH+1)

    int b  = blockIdx.y;
    int p0 = blockIdx.x * 32;
    int t  = threadIdx.x;
    int h  = t >> 4;
    int pl = t & 15;
    int pa = p0 + pl;
    int pb = p0 + pl + 16;
    bool va = (pa < P_), vb = (pb < P_);

    float4 qa[4], qb[4];
    {
        const float4* qpa = (const float4*)(Q + ((size_t)b * P_ + (va ? pa : 0)) * HD_ + h * D_);
        const float4* qpb = (const float4*)(Q + ((size_t)b * P_ + (vb ? pb : 0)) * HD_ + h * D_);
#pragma unroll
        for (int i = 0; i < 4; i++) {
            qa[i] = va ? qpa[i] : make_float4(0.f, 0.f, 0.f, 0.f);
            qb[i] = vb ? qpb[i] : make_float4(0.f, 0.f, 0.f, 0.f);
        }
    }

    float ma = -INFINITY, sa = 0.f;
    float mb = -INFINITY, sb = 0.f;
    float4 oa[4] = {}, ob[4] = {};

    for (int n0 = 0; n0 < N_; n0 += ACH) {
        int nn = min(ACH, N_ - n0);            // tail: 1000 = 62*16 + 8
        {   // cooperative K/V chunk load
            const float4* Kg = (const float4*)(K + ((size_t)b * N_ + n0) * HD_);
            const float4* Vg = (const float4*)(V + ((size_t)b * N_ + n0) * HD_);
            float4* k4 = (float4*)k_sm;
            float4* v4 = (float4*)v_sm;
            int tot = nn * (HD_ / 4);
            for (int i = t; i < tot; i += 256) { k4[i] = Kg[i]; v4[i] = Vg[i]; }
            for (int i = t; i < 32 * ACH; i += 256) {
                int r = i >> 4, c = i & (ACH - 1);
                float mv = 0.f;
                if (p0 + r < P_ && c < nn)
                    mv = mask[((size_t)b * P_ + p0 + r) * N_ + n0 + c];
                m_sm[r * (ACH + 1) + c] = mv;
            }
        }
        __syncthreads();

        float sca[ACH], scb[ACH];
        float cma = -INFINITY, cmb = -INFINITY;
#pragma unroll
        for (int j = 0; j < ACH; j++) {
            const float4* kp = (const float4*)(k_sm + j * HD_ + h * D_);
            float4 k0v = kp[0], k1v = kp[1], k2v = kp[2], k3v = kp[3];
            float ca, cb;
            ca  = qa[0].x * k0v.x + qa[0].y * k0v.y + qa[0].z * k0v.z + qa[0].w * k0v.w;
            ca += qa[1].x * k1v.x + qa[1].y * k1v.y + qa[1].z * k1v.z + qa[1].w * k1v.w;
            ca += qa[2].x * k2v.x + qa[2].y * k2v.y + qa[2].z * k2v.z + qa[2].w * k2v.w;
            ca += qa[3].x * k3v.x + qa[3].y * k3v.y + qa[3].z * k3v.z + qa[3].w * k3v.w;
            cb  = qb[0].x * k0v.x + qb[0].y * k0v.y + qb[0].z * k0v.z + qb[0].w * k0v.w;
            cb += qb[1].x * k1v.x + qb[1].y * k1v.y + qb[1].z * k1v.z + qb[1].w * k1v.w;
            cb += qb[2].x * k2v.x + qb[2].y * k2v.y + qb[2].z * k2v.z + qb[2].w * k2v.w;
            cb += qb[3].x * k3v.x + qb[3].y * k3v.y + qb[3].z * k3v.z + qb[3].w * k3v.w;
            ca = ca * 0.25f + m_sm[pl * (ACH + 1) + j];
            cb = cb * 0.25f + m_sm[(pl + 16) * (ACH + 1) + j];
            sca[j] = (j < nn) ? ca : -INFINITY;
            scb[j] = (j < nn) ? cb : -INFINITY;
            cma = fmaxf(cma, sca[j]);
            cmb = fmaxf(cmb, scb[j]);
        }
        float mna = fmaxf(ma, cma), mnb = fmaxf(mb, cmb);
        float fa = __expf(ma - mna), fb = __expf(mb - mnb);
        sa *= fa; sb *= fb;
#pragma unroll
        for (int i = 0; i < 4; i++) {
            oa[i].x *= fa; oa[i].y *= fa; oa[i].z *= fa; oa[i].w *= fa;
            ob[i].x *= fb; ob[i].y *= fb; ob[i].z *= fb; ob[i].w *= fb;
        }
#pragma unroll
        for (int j = 0; j < ACH; j++) {
            float wa = __expf(sca[j] - mna);
            float wb = __expf(scb[j] - mnb);
            sa += wa; sb += wb;
            const float4* vp = (const float4*)(v_sm + j * HD_ + h * D_);
            float4 v0 = vp[0], v1 = vp[1], v2 = vp[2], v3 = vp[3];
            oa[0].x += wa * v0.x; oa[0].y += wa * v0.y; oa[0].z += wa * v0.z; oa[0].w += wa * v0.w;
            oa[1].x += wa * v1.x; oa[1].y += wa * v1.y; oa[1].z += wa * v1.z; oa[1].w += wa * v1.w;
            oa[2].x += wa * v2.x; oa[2].y += wa * v2.y; oa[2].z += wa * v2.z; oa[2].w += wa * v2.w;
            oa[3].x += wa * v3.x; oa[3].y += wa * v3.y; oa[3].z += wa * v3.z; oa[3].w += wa * v3.w;
            ob[0].x += wb * v0.x; ob[0].y += wb * v0.y; ob[0].z += wb * v0.z; ob[0].w += wb * v0.w;
            ob[1].x += wb * v1.x; ob[1].y += wb * v1.y; ob[1].z += wb * v1.z; ob[1].w += wb * v1.w;
            ob[2].x += wb * v2.x; ob[2].y += wb * v2.y; ob[2].z += wb * v2.z; ob[2].w += wb * v2.w;
            ob[3].x += wb * v3.x; ob[3].y += wb * v3.y; ob[3].z += wb * v3.z; ob[3].w += wb * v3.w;
        }
        ma = mna; mb = mnb;
        __syncthreads();
    }

    if (va) {
        float inv = 1.f / sa;
        float4* op = (float4*)(OC + ((size_t)b * P_ + pa) * HD_ + h * D_);
#pragma unroll
        for (int i = 0; i < 4; i++) {
            float4 o = oa[i];
            o.x *= inv; o.y *= inv; o.z *= inv; o.w *= inv;
            op[i] = o;
        }
    }
    if (vb) {
        float inv = 1.f / sb;
        float4* op = (float4*)(OC + ((size_t)b * P_ + pb) * HD_ + h * D_);
#pragma unroll
        for (int i = 0; i < 4; i++) {
            float4 o = ob[i];
            o.x *= inv; o.y *= inv; o.z *= inv; o.w *= inv;
            op[i] = o;
        }
    }
}

// ---------------- row softmax over S: one block per row ----------------
__global__ void __launch_bounds__(256)
softmax_k(const float* __restrict__ S, float* __restrict__ out)
{
    __shared__ float red[8];
    size_t row = blockIdx.x;                  // 0 .. B_*P_-1
    const float* src = S   + row * N_;
    float*       dst = out + row * N_;
    int t = threadIdx.x;
    int lane = t & 31, w = t >> 5;

    float v[4];
    float lm = -INFINITY;
#pragma unroll
    for (int i = 0; i < 4; i++) {
        int n = t + i * 256;
        v[i] = (n < N_) ? src[n] : -INFINITY;
        lm = fmaxf(lm, v[i]);
    }
#pragma unroll
    for (int o = 16; o; o >>= 1) lm = fmaxf(lm, __shfl_xor_sync(~0u, lm, o));
    if (lane == 0) red[w] = lm;
    __syncthreads();
    lm = red[lane & 7];
#pragma unroll
    for (int o = 4; o; o >>= 1) lm = fmaxf(lm, __shfl_xor_sync(~0u, lm, o));
    float M = lm;

    float ls = 0.f;
#pragma unroll
    for (int i = 0; i < 4; i++) {
        v[i] = __expf(v[i] - M);
        ls += v[i];
    }
#pragma unroll
    for (int o = 16; o; o >>= 1) ls += __shfl_xor_sync(~0u, ls, o);
    __syncthreads();
    if (lane == 0) red[w] = ls;
    __syncthreads();
    ls = red[lane & 7];
#pragma unroll
    for (int o = 4; o; o >>= 1) ls += __shfl_xor_sync(~0u, ls, o);
    float inv = 1.f / ls;

#pragma unroll
    for (int i = 0; i < 4; i++) {
        int n = t + i * 256;
        if (n < N_) dst[n] = v[i] * inv;
    }
}

// ---------------- launch ----------------
static const int ATTN_SMEM = (ACH * HD_ * 2 + 32 * (ACH + 1)) * (int)sizeof(float);

extern "C" void kernel_launch(void* const* d_in, const int* in_sizes, int n_in,
                              void* d_out, int out_size)
{
    const float* eln  = (const float*)d_in[0];
    const float* attr = (const float*)d_in[1];
    const float* mask = (const float*)d_in[2];
    const float* enc  = (const float*)d_in[3];
    const float* Wq   = (const float*)d_in[4];  // [257, 256]
    const float* Wk   = (const float*)d_in[5];
    const float* Wv   = (const float*)d_in[6];
    const float* Wc   = (const float*)d_in[7];
    const float* bc   = (const float*)d_in[8];
    float* out = (float*)d_out;

    float *Kp, *Vp, *Qp, *OCp, *MHp, *Sp;
    cudaGetSymbolAddress((void**)&Kp,  g_K);
    cudaGetSymbolAddress((void**)&Vp,  g_V);
    cudaGetSymbolAddress((void**)&Qp,  g_Q);
    cudaGetSymbolAddress((void**)&OCp, g_OC);
    cudaGetSymbolAddress((void**)&MHp, g_MH);
    cudaGetSymbolAddress((void**)&Sp,  g_S);

    cudaFuncSetAttribute(attn_k, cudaFuncAttributeMaxDynamicSharedMemorySize, ATTN_SMEM);

    dim3 gg(HD_ / GN, (B_ * N_) / GM);   // (2, 125)

    // projections (DRAM is 3% — 128x128 tiles, conflict-free fragments)
    gemm128<<<gg, 256>>>(enc, Wk, Kp, HD_, nullptr, nullptr, nullptr);
    gemm128<<<gg, 256>>>(enc, Wv, Vp, HD_, nullptr, nullptr, nullptr);
    gemm128<<<gg, 256>>>(eln, Wq, Qp, HD_, nullptr, attr, Wq + 256 * 256);

    // fused MHA (32 p per block, 2 p per thread)
    attn_k<<<dim3((P_ + 31) / 32, B_), 256, ATTN_SMEM>>>(Qp, Kp, Vp, mask, OCp);

    // output projection
    gemm128<<<gg, 256>>>(OCp, Wc, MHp, E_, bc, nullptr, nullptr);

    // probe score GEMM (+ tanh/mask epilogue) then row softmax
    dim3 gp((N_ + GN - 1) / GN, (P_ + GM - 1) / GM, B_);   // (8, 8, 16)
    abT128  <<<gp, 256>>>(MHp, enc, mask, Sp);
    softmax_k<<<B_ * P_, 256>>>(Sp, out);
}

// round 8
// speedup vs baseline: 1.5434x; 1.5434x over previous
#include <cuda_runtime.h>
#include <math.h>
#include <stdint.h>

// Problem dims (fixed per metadata)
#define B_  16
#define P_  1000
#define N_  1000
#define E_  256
#define HD_ 256
#define H_  16
#define D_  16

// ---------------- scratch (no allocations allowed) ----------------
__device__ float g_K [B_ * N_ * HD_];
__device__ float g_V [B_ * N_ * HD_];
__device__ float g_Q [B_ * P_ * HD_];
__device__ float g_OC[B_ * P_ * HD_];
__device__ float g_MH[B_ * P_ * E_ ];
__device__ float g_S [(size_t)B_ * P_ * N_];   // 64 MB score scratch

// ================= 128x64x16 fp32 GEMM, 8x4 microtile =================
// 256 threads: ty=tid>>4 (8-row strip), tx=tid&15 (4-col strip).
// Per k-step: 2 broadcast LDS.128 (A) + 1 conflict-free LDS.128 (B: 16B*tx
// spans all 32 banks over 16 lanes) feed 32 FFMA. ~70 regs -> ~3 blocks/SM.
#define GM 128
#define GN 64
#define GK 16

__global__ void __launch_bounds__(256)
gemm2(const float* __restrict__ A, const float* __restrict__ Bw,
      float* __restrict__ C, int Nc,
      const float* __restrict__ bias,
      const float* __restrict__ attr,
      const float* __restrict__ attr_row)
{
    __shared__ float As[GK][GM + 4];
    __shared__ float Bs[GK][GN];
    const int Kdim = 256;
    int tid = threadIdx.x;
    int tx = tid & 15, ty = tid >> 4;
    int m0 = blockIdx.y * GM;
    int n0 = blockIdx.x * GN;

    int ar  = tid >> 1;            // 0..127 (A row)
    int akq = (tid & 1) * 8;       // 0 or 8 (A k offset)
    int bk  = tid >> 4;            // 0..15  (B k row)
    int bc  = (tid & 15) * 4;      // B col offset

    float acc[8][4] = {};

    for (int k0 = 0; k0 < Kdim; k0 += GK) {
        {   // A tile: 128 rows x 16 k, stored transposed
            const float* Ap = A + (size_t)(m0 + ar) * Kdim + k0 + akq;
            float4 a0 = *(const float4*)(Ap);
            float4 a1 = *(const float4*)(Ap + 4);
            As[akq + 0][ar] = a0.x; As[akq + 1][ar] = a0.y;
            As[akq + 2][ar] = a0.z; As[akq + 3][ar] = a0.w;
            As[akq + 4][ar] = a1.x; As[akq + 5][ar] = a1.y;
            As[akq + 6][ar] = a1.z; As[akq + 7][ar] = a1.w;
        }
        {   // B tile: 16 k x 64 n, contiguous
            *(float4*)(&Bs[bk][bc]) =
                *(const float4*)(Bw + (size_t)(k0 + bk) * Nc + n0 + bc);
        }
        __syncthreads();
#pragma unroll
        for (int k = 0; k < GK; k++) {
            float a[8], b[4];
            *(float4*)(a)     = *(const float4*)(&As[k][ty * 8]);
            *(float4*)(a + 4) = *(const float4*)(&As[k][ty * 8 + 4]);
            *(float4*)(b)     = *(const float4*)(&Bs[k][tx * 4]);
#pragma unroll
            for (int i = 0; i < 8; i++)
#pragma unroll
                for (int j = 0; j < 4; j++)
                    acc[i][j] = fmaf(a[i], b[j], acc[i][j]);
        }
        __syncthreads();
    }

#pragma unroll
    for (int i = 0; i < 8; i++) {
        int m = m0 + ty * 8 + i;
        float am = attr ? attr[m] : 0.f;
        float4 v;
        float* vv = (float*)&v;
#pragma unroll
        for (int j = 0; j < 4; j++) {
            int n = n0 + tx * 4 + j;
            float x = acc[i][j];
            if (bias) x += bias[n];
            if (attr) x += am * attr_row[n];
            vv[j] = x;
        }
        *(float4*)(C + (size_t)m * Nc + n0 + tx * 4) = v;
    }
}

// ======= probe score GEMM (A·B^T), 128x64 tile, 8x4 microtile, fused epilogue =======
// S[b] = 10*tanh((MH[b] @ enc[b]^T)/16) + mask[b];  M=P_, N=N_, K=256.
__global__ void __launch_bounds__(256)
abT2(const float* __restrict__ MH, const float* __restrict__ enc,
     const float* __restrict__ mask, float* __restrict__ S)
{
    __shared__ float As[GK][GM + 4];
    __shared__ float Bs[GK][GN + 4];
    const int Kdim = 256;
    int b   = blockIdx.z;
    int tid = threadIdx.x;
    int tx = tid & 15, ty = tid >> 4;
    int m0 = blockIdx.y * GM;
    int n0 = blockIdx.x * GN;

    const float* A  = MH  + (size_t)b * P_ * E_;
    const float* Bm = enc + (size_t)b * N_ * E_;

    int ar  = tid >> 1;            // 0..127
    int akq = (tid & 1) * 8;
    int br  = tid >> 2;            // 0..63  (B n-row)
    int bkq = (tid & 3) * 4;       // 0,4,8,12

    float acc[8][4] = {};

    for (int k0 = 0; k0 < Kdim; k0 += GK) {
        {   // A tile (row clamp for 1000 = 7*128 + 104 tail)
            int m = m0 + ar; if (m >= P_) m = P_ - 1;
            const float* Ap = A + (size_t)m * Kdim + k0 + akq;
            float4 a0 = *(const float4*)(Ap);
            float4 a1 = *(const float4*)(Ap + 4);
            As[akq + 0][ar] = a0.x; As[akq + 1][ar] = a0.y;
            As[akq + 2][ar] = a0.z; As[akq + 3][ar] = a0.w;
            As[akq + 4][ar] = a1.x; As[akq + 5][ar] = a1.y;
            As[akq + 6][ar] = a1.z; As[akq + 7][ar] = a1.w;
        }
        {   // B tile: 64 n-rows x 16 k, transposed staging (row clamp)
            int n = n0 + br; if (n >= N_) n = N_ - 1;
            float4 b4 = *(const float4*)(Bm + (size_t)n * Kdim + k0 + bkq);
            Bs[bkq + 0][br] = b4.x; Bs[bkq + 1][br] = b4.y;
            Bs[bkq + 2][br] = b4.z; Bs[bkq + 3][br] = b4.w;
        }
        __syncthreads();
#pragma unroll
        for (int k = 0; k < GK; k++) {
            float a[8], bb[4];
            *(float4*)(a)     = *(const float4*)(&As[k][ty * 8]);
            *(float4*)(a + 4) = *(const float4*)(&As[k][ty * 8 + 4]);
            *(float4*)(bb)    = *(const float4*)(&Bs[k][tx * 4]);
#pragma unroll
            for (int i = 0; i < 8; i++)
#pragma unroll
                for (int j = 0; j < 4; j++)
                    acc[i][j] = fmaf(a[i], bb[j], acc[i][j]);
        }
        __syncthreads();
    }

#pragma unroll
    for (int i = 0; i < 8; i++) {
        int m = m0 + ty * 8 + i;
        if (m >= P_) continue;
#pragma unroll
        for (int j = 0; j < 4; j++) {
            int n = n0 + tx * 4 + j;
            if (n >= N_) continue;
            size_t idx = ((size_t)b * P_ + m) * N_ + n;
            S[idx] = 10.f * tanhf(acc[i][j] * 0.0625f) + mask[idx];
        }
    }
}

// ---------------- fused multi-head attention (flash style, 2 p-rows / thread) ----------------
// (unchanged from the measured 1234us build)
#define ACH 16

__global__ void __launch_bounds__(256)
attn_k(const float* __restrict__ Q, const float* __restrict__ K,
       const float* __restrict__ V, const float* __restrict__ mask,
       float* __restrict__ OC)
{
    extern __shared__ float sm[];
    float* k_sm = sm;                          // ACH * 256
    float* v_sm = k_sm + ACH * HD_;            // ACH * 256
    float* m_sm = v_sm + ACH * HD_;            // 32 * (ACH+1)

    int b  = blockIdx.y;
    int p0 = blockIdx.x * 32;
    int t  = threadIdx.x;
    int h  = t >> 4;
    int pl = t & 15;
    int pa = p0 + pl;
    int pb = p0 + pl + 16;
    bool va = (pa < P_), vb = (pb < P_);

    float4 qa[4], qb[4];
    {
        const float4* qpa = (const float4*)(Q + ((size_t)b * P_ + (va ? pa : 0)) * HD_ + h * D_);
        const float4* qpb = (const float4*)(Q + ((size_t)b * P_ + (vb ? pb : 0)) * HD_ + h * D_);
#pragma unroll
        for (int i = 0; i < 4; i++) {
            qa[i] = va ? qpa[i] : make_float4(0.f, 0.f, 0.f, 0.f);
            qb[i] = vb ? qpb[i] : make_float4(0.f, 0.f, 0.f, 0.f);
        }
    }

    float ma = -INFINITY, sa = 0.f;
    float mb = -INFINITY, sb = 0.f;
    float4 oa[4] = {}, ob[4] = {};

    for (int n0 = 0; n0 < N_; n0 += ACH) {
        int nn = min(ACH, N_ - n0);            // tail: 1000 = 62*16 + 8
        {   // cooperative K/V chunk load
            const float4* Kg = (const float4*)(K + ((size_t)b * N_ + n0) * HD_);
            const float4* Vg = (const float4*)(V + ((size_t)b * N_ + n0) * HD_);
            float4* k4 = (float4*)k_sm;
            float4* v4 = (float4*)v_sm;
            int tot = nn * (HD_ / 4);
            for (int i = t; i < tot; i += 256) { k4[i] = Kg[i]; v4[i] = Vg[i]; }
            for (int i = t; i < 32 * ACH; i += 256) {
                int r = i >> 4, c = i & (ACH - 1);
                float mv = 0.f;
                if (p0 + r < P_ && c < nn)
                    mv = mask[((size_t)b * P_ + p0 + r) * N_ + n0 + c];
                m_sm[r * (ACH + 1) + c] = mv;
            }
        }
        __syncthreads();

        float sca[ACH], scb[ACH];
        float cma = -INFINITY, cmb = -INFINITY;
#pragma unroll
        for (int j = 0; j < ACH; j++) {
            const float4* kp = (const float4*)(k_sm + j * HD_ + h * D_);
            float4 k0v = kp[0], k1v = kp[1], k2v = kp[2], k3v = kp[3];
            float ca, cb;
            ca  = qa[0].x * k0v.x + qa[0].y * k0v.y + qa[0].z * k0v.z + qa[0].w * k0v.w;
            ca += qa[1].x * k1v.x + qa[1].y * k1v.y + qa[1].z * k1v.z + qa[1].w * k1v.w;
            ca += qa[2].x * k2v.x + qa[2].y * k2v.y + qa[2].z * k2v.z + qa[2].w * k2v.w;
            ca += qa[3].x * k3v.x + qa[3].y * k3v.y + qa[3].z * k3v.z + qa[3].w * k3v.w;
            cb  = qb[0].x * k0v.x + qb[0].y * k0v.y + qb[0].z * k0v.z + qb[0].w * k0v.w;
            cb += qb[1].x * k1v.x + qb[1].y * k1v.y + qb[1].z * k1v.z + qb[1].w * k1v.w;
            cb += qb[2].x * k2v.x + qb[2].y * k2v.y + qb[2].z * k2v.z + qb[2].w * k2v.w;
            cb += qb[3].x * k3v.x + qb[3].y * k3v.y + qb[3].z * k3v.z + qb[3].w * k3v.w;
            ca = ca * 0.25f + m_sm[pl * (ACH + 1) + j];
            cb = cb * 0.25f + m_sm[(pl + 16) * (ACH + 1) + j];
            sca[j] = (j < nn) ? ca : -INFINITY;
            scb[j] = (j < nn) ? cb : -INFINITY;
            cma = fmaxf(cma, sca[j]);
            cmb = fmaxf(cmb, scb[j]);
        }
        float mna = fmaxf(ma, cma), mnb = fmaxf(mb, cmb);
        float fa = __expf(ma - mna), fb = __expf(mb - mnb);
        sa *= fa; sb *= fb;
#pragma unroll
        for (int i = 0; i < 4; i++) {
            oa[i].x *= fa; oa[i].y *= fa; oa[i].z *= fa; oa[i].w *= fa;
            ob[i].x *= fb; ob[i].y *= fb; ob[i].z *= fb; ob[i].w *= fb;
        }
#pragma unroll
        for (int j = 0; j < ACH; j++) {
            float wa = __expf(sca[j] - mna);
            float wb = __expf(scb[j] - mnb);
            sa += wa; sb += wb;
            const float4* vp = (const float4*)(v_sm + j * HD_ + h * D_);
            float4 v0 = vp[0], v1 = vp[1], v2 = vp[2], v3 = vp[3];
            oa[0].x += wa * v0.x; oa[0].y += wa * v0.y; oa[0].z += wa * v0.z; oa[0].w += wa * v0.w;
            oa[1].x += wa * v1.x; oa[1].y += wa * v1.y; oa[1].z += wa * v1.z; oa[1].w += wa * v1.w;
            oa[2].x += wa * v2.x; oa[2].y += wa * v2.y; oa[2].z += wa * v2.z; oa[2].w += wa * v2.w;
            oa[3].x += wa * v3.x; oa[3].y += wa * v3.y; oa[3].z += wa * v3.z; oa[3].w += wa * v3.w;
            ob[0].x += wb * v0.x; ob[0].y += wb * v0.y; ob[0].z += wb * v0.z; ob[0].w += wb * v0.w;
            ob[1].x += wb * v1.x; ob[1].y += wb * v1.y; ob[1].z += wb * v1.z; ob[1].w += wb * v1.w;
            ob[2].x += wb * v2.x; ob[2].y += wb * v2.y; ob[2].z += wb * v2.z; ob[2].w += wb * v2.w;
            ob[3].x += wb * v3.x; ob[3].y += wb * v3.y; ob[3].z += wb * v3.z; ob[3].w += wb * v3.w;
        }
        ma = mna; mb = mnb;
        __syncthreads();
    }

    if (va) {
        float inv = 1.f / sa;
        float4* op = (float4*)(OC + ((size_t)b * P_ + pa) * HD_ + h * D_);
#pragma unroll
        for (int i = 0; i < 4; i++) {
            float4 o = oa[i];
            o.x *= inv; o.y *= inv; o.z *= inv; o.w *= inv;
            op[i] = o;
        }
    }
    if (vb) {
        float inv = 1.f / sb;
        float4* op = (float4*)(OC + ((size_t)b * P_ + pb) * HD_ + h * D_);
#pragma unroll
        for (int i = 0; i < 4; i++) {
            float4 o = ob[i];
            o.x *= inv; o.y *= inv; o.z *= inv; o.w *= inv;
            op[i] = o;
        }
    }
}

// ---------------- row softmax over S: one block per row ----------------
__global__ void __launch_bounds__(256)
softmax_k(const float* __restrict__ S, float* __restrict__ out)
{
    __shared__ float red[8];
    size_t row = blockIdx.x;                  // 0 .. B_*P_-1
    const float* src = S   + row * N_;
    float*       dst = out + row * N_;
    int t = threadIdx.x;
    int lane = t & 31, w = t >> 5;

    float v[4];
    float lm = -INFINITY;
#pragma unroll
    for (int i = 0; i < 4; i++) {
        int n = t + i * 256;
        v[i] = (n < N_) ? src[n] : -INFINITY;
        lm = fmaxf(lm, v[i]);
    }
#pragma unroll
    for (int o = 16; o; o >>= 1) lm = fmaxf(lm, __shfl_xor_sync(~0u, lm, o));
    if (lane == 0) red[w] = lm;
    __syncthreads();
    lm = red[lane & 7];
#pragma unroll
    for (int o = 4; o; o >>= 1) lm = fmaxf(lm, __shfl_xor_sync(~0u, lm, o));
    float M = lm;

    float ls = 0.f;
#pragma unroll
    for (int i = 0; i < 4; i++) {
        v[i] = __expf(v[i] - M);
        ls += v[i];
    }
#pragma unroll
    for (int o = 16; o; o >>= 1) ls += __shfl_xor_sync(~0u, ls, o);
    __syncthreads();
    if (lane == 0) red[w] = ls;
    __syncthreads();
    ls = red[lane & 7];
#pragma unroll
    for (int o = 4; o; o >>= 1) ls += __shfl_xor_sync(~0u, ls, o);
    float inv = 1.f / ls;

#pragma unroll
    for (int i = 0; i < 4; i++) {
        int n = t + i * 256;
        if (n < N_) dst[n] = v[i] * inv;
    }
}

// ---------------- launch ----------------
static const int ATTN_SMEM = (ACH * HD_ * 2 + 32 * (ACH + 1)) * (int)sizeof(float);

extern "C" void kernel_launch(void* const* d_in, const int* in_sizes, int n_in,
                              void* d_out, int out_size)
{
    const float* eln  = (const float*)d_in[0];
    const float* attr = (const float*)d_in[1];
    const float* mask = (const float*)d_in[2];
    const float* enc  = (const float*)d_in[3];
    const float* Wq   = (const float*)d_in[4];  // [257, 256]
    const float* Wk   = (const float*)d_in[5];
    const float* Wv   = (const float*)d_in[6];
    const float* Wc   = (const float*)d_in[7];
    const float* bc   = (const float*)d_in[8];
    float* out = (float*)d_out;

    float *Kp, *Vp, *Qp, *OCp, *MHp, *Sp;
    cudaGetSymbolAddress((void**)&Kp,  g_K);
    cudaGetSymbolAddress((void**)&Vp,  g_V);
    cudaGetSymbolAddress((void**)&Qp,  g_Q);
    cudaGetSymbolAddress((void**)&OCp, g_OC);
    cudaGetSymbolAddress((void**)&MHp, g_MH);
    cudaGetSymbolAddress((void**)&Sp,  g_S);

    cudaFuncSetAttribute(attn_k, cudaFuncAttributeMaxDynamicSharedMemorySize, ATTN_SMEM);

    dim3 gg(HD_ / GN, (B_ * N_) / GM);   // (4, 125)

    // projections: 128x64 tiles, 8x4 microtile
    gemm2<<<gg, 256>>>(enc, Wk, Kp, HD_, nullptr, nullptr, nullptr);
    gemm2<<<gg, 256>>>(enc, Wv, Vp, HD_, nullptr, nullptr, nullptr);
    gemm2<<<gg, 256>>>(eln, Wq, Qp, HD_, nullptr, attr, Wq + 256 * 256);

    // fused MHA (32 p per block, 2 p per thread)
    attn_k<<<dim3((P_ + 31) / 32, B_), 256, ATTN_SMEM>>>(Qp, Kp, Vp, mask, OCp);

    // output projection
    gemm2<<<gg, 256>>>(OCp, Wc, MHp, E_, bc, nullptr, nullptr);

    // probe score GEMM (+ tanh/mask epilogue) then row softmax
    dim3 gp((N_ + GN - 1) / GN, (P_ + GM - 1) / GM, B_);   // (16, 8, 16)
    abT2     <<<gp, 256>>>(MHp, enc, mask, Sp);
    softmax_k<<<B_ * P_, 256>>>(Sp, out);
}

// round 11
// speedup vs baseline: 1.6997x; 1.1013x over previous
#include <cuda_runtime.h>
#include <math.h>
#include <stdint.h>

// Problem dims (fixed per metadata)
#define B_  16
#define P_  1000
#define N_  1000
#define E_  256
#define HD_ 256
#define H_  16
#define D_  16

// ---------------- scratch (no allocations allowed) ----------------
__device__ float g_K [B_ * N_ * HD_];
__device__ float g_V [B_ * N_ * HD_];
__device__ float g_Q [B_ * P_ * HD_];
__device__ float g_OC[B_ * P_ * HD_];
__device__ float g_MH[B_ * P_ * E_ ];
__device__ float g_S [(size_t)B_ * P_ * N_];   // 64 MB score scratch

// ================= 128x64x16 fp32 GEMM, 8x4 microtile (measured-good) =================
#define GM 128
#define GN 64
#define GK 16

__global__ void __launch_bounds__(256)
gemm2(const float* __restrict__ A, const float* __restrict__ Bw,
      float* __restrict__ C, int Nc,
      const float* __restrict__ bias,
      const float* __restrict__ attr,
      const float* __restrict__ attr_row)
{
    __shared__ float As[GK][GM + 4];
    __shared__ float Bs[GK][GN];
    const int Kdim = 256;
    int tid = threadIdx.x;
    int tx = tid & 15, ty = tid >> 4;
    int m0 = blockIdx.y * GM;
    int n0 = blockIdx.x * GN;

    int ar  = tid >> 1;
    int akq = (tid & 1) * 8;
    int bk  = tid >> 4;
    int bc  = (tid & 15) * 4;

    float acc[8][4] = {};

    for (int k0 = 0; k0 < Kdim; k0 += GK) {
        {
            const float* Ap = A + (size_t)(m0 + ar) * Kdim + k0 + akq;
            float4 a0 = *(const float4*)(Ap);
            float4 a1 = *(const float4*)(Ap + 4);
            As[akq + 0][ar] = a0.x; As[akq + 1][ar] = a0.y;
            As[akq + 2][ar] = a0.z; As[akq + 3][ar] = a0.w;
            As[akq + 4][ar] = a1.x; As[akq + 5][ar] = a1.y;
            As[akq + 6][ar] = a1.z; As[akq + 7][ar] = a1.w;
        }
        {
            *(float4*)(&Bs[bk][bc]) =
                *(const float4*)(Bw + (size_t)(k0 + bk) * Nc + n0 + bc);
        }
        __syncthreads();
#pragma unroll
        for (int k = 0; k < GK; k++) {
            float a[8], b[4];
            *(float4*)(a)     = *(const float4*)(&As[k][ty * 8]);
            *(float4*)(a + 4) = *(const float4*)(&As[k][ty * 8 + 4]);
            *(float4*)(b)     = *(const float4*)(&Bs[k][tx * 4]);
#pragma unroll
            for (int i = 0; i < 8; i++)
#pragma unroll
                for (int j = 0; j < 4; j++)
                    acc[i][j] = fmaf(a[i], b[j], acc[i][j]);
        }
        __syncthreads();
    }

#pragma unroll
    for (int i = 0; i < 8; i++) {
        int m = m0 + ty * 8 + i;
        float am = attr ? attr[m] : 0.f;
        float4 v;
        float* vv = (float*)&v;
#pragma unroll
        for (int j = 0; j < 4; j++) {
            int n = n0 + tx * 4 + j;
            float x = acc[i][j];
            if (bias) x += bias[n];
            if (attr) x += am * attr_row[n];
            vv[j] = x;
        }
        *(float4*)(C + (size_t)m * Nc + n0 + tx * 4) = v;
    }
}

// ======= probe score GEMM (A·B^T), 128x64 tile, 8x4 microtile, fused epilogue =======
__global__ void __launch_bounds__(256)
abT2(const float* __restrict__ MH, const float* __restrict__ enc,
     const float* __restrict__ mask, float* __restrict__ S)
{
    __shared__ float As[GK][GM + 4];
    __shared__ float Bs[GK][GN + 4];
    const int Kdim = 256;
    int b   = blockIdx.z;
    int tid = threadIdx.x;
    int tx = tid & 15, ty = tid >> 4;
    int m0 = blockIdx.y * GM;
    int n0 = blockIdx.x * GN;

    const float* A  = MH  + (size_t)b * P_ * E_;
    const float* Bm = enc + (size_t)b * N_ * E_;

    int ar  = tid >> 1;
    int akq = (tid & 1) * 8;
    int br  = tid >> 2;
    int bkq = (tid & 3) * 4;

    float acc[8][4] = {};

    for (int k0 = 0; k0 < Kdim; k0 += GK) {
        {
            int m = m0 + ar; if (m >= P_) m = P_ - 1;
            const float* Ap = A + (size_t)m * Kdim + k0 + akq;
            float4 a0 = *(const float4*)(Ap);
            float4 a1 = *(const float4*)(Ap + 4);
            As[akq + 0][ar] = a0.x; As[akq + 1][ar] = a0.y;
            As[akq + 2][ar] = a0.z; As[akq + 3][ar] = a0.w;
            As[akq + 4][ar] = a1.x; As[akq + 5][ar] = a1.y;
            As[akq + 6][ar] = a1.z; As[akq + 7][ar] = a1.w;
        }
        {
            int n = n0 + br; if (n >= N_) n = N_ - 1;
            float4 b4 = *(const float4*)(Bm + (size_t)n * Kdim + k0 + bkq);
            Bs[bkq + 0][br] = b4.x; Bs[bkq + 1][br] = b4.y;
            Bs[bkq + 2][br] = b4.z; Bs[bkq + 3][br] = b4.w;
        }
        __syncthreads();
#pragma unroll
        for (int k = 0; k < GK; k++) {
            float a[8], bb[4];
            *(float4*)(a)     = *(const float4*)(&As[k][ty * 8]);
            *(float4*)(a + 4) = *(const float4*)(&As[k][ty * 8 + 4]);
            *(float4*)(bb)    = *(const float4*)(&Bs[k][tx * 4]);
#pragma unroll
            for (int i = 0; i < 8; i++)
#pragma unroll
                for (int j = 0; j < 4; j++)
                    acc[i][j] = fmaf(a[i], bb[j], acc[i][j]);
        }
        __syncthreads();
    }

#pragma unroll
    for (int i = 0; i < 8; i++) {
        int m = m0 + ty * 8 + i;
        if (m >= P_) continue;
#pragma unroll
        for (int j = 0; j < 4; j++) {
            int n = n0 + tx * 4 + j;
            if (n >= N_) continue;
            size_t idx = ((size_t)b * P_ + m) * N_ + n;
            S[idx] = 10.f * tanhf(acc[i][j] * 0.0625f) + mask[idx];
        }
    }
}

// ---------------- fused MHA: cp.async double-buffered K/V/mask chunks ----------------
#define ACH 16
#define MST 20                         // mask row stride (16B-aligned for cp.async)
#define KOFF 0
#define VOFF (ACH * HD_)               // 4096 floats
#define MOFF (2 * ACH * HD_)           // 8192 floats
#define BUFF (2 * ACH * HD_ + 32 * MST) // 8832 floats per buffer

__device__ __forceinline__ void cpa16(uint32_t dst, const void* src) {
    asm volatile("cp.async.cg.shared.global [%0], [%1], 16;" :: "r"(dst), "l"(src));
}

__global__ void __launch_bounds__(256)
attn_k(const float* __restrict__ Q, const float* __restrict__ K,
       const float* __restrict__ V, const float* __restrict__ mask,
       float* __restrict__ OC)
{
    extern __shared__ float sm[];
    int b  = blockIdx.y;
    int p0 = blockIdx.x * 32;
    int t  = threadIdx.x;
    int h  = t >> 4;
    int pl = t & 15;
    int pa = p0 + pl;
    int pb = p0 + pl + 16;
    bool va = (pa < P_), vb = (pb < P_);

    uint32_t smb = (uint32_t)__cvta_generic_to_shared(sm);

    float4 qa[4], qb[4];
    {
        const float4* qpa = (const float4*)(Q + ((size_t)b * P_ + (va ? pa : 0)) * HD_ + h * D_);
        const float4* qpb = (const float4*)(Q + ((size_t)b * P_ + (vb ? pb : 0)) * HD_ + h * D_);
#pragma unroll
        for (int i = 0; i < 4; i++) {
            qa[i] = va ? qpa[i] : make_float4(0.f, 0.f, 0.f, 0.f);
            qb[i] = vb ? qpb[i] : make_float4(0.f, 0.f, 0.f, 0.f);
        }
    }

    // ---- prefetch chunk starting at n0 into buffer `buf` ----
    auto prefetch = [&](int n0, int buf) {
        int nn = min(ACH, N_ - n0);
        uint32_t db = smb + (uint32_t)(buf * BUFF) * 4u;
        const float* Kg = K + ((size_t)b * N_ + n0) * HD_;
        const float* Vg = V + ((size_t)b * N_ + n0) * HD_;
        int tot = nn * (HD_ / 4);                    // float4 count
        for (int i = t; i < tot; i += 256) {
            cpa16(db + (uint32_t)(KOFF + i * 4) * 4u, Kg + i * 4);
            cpa16(db + (uint32_t)(VOFF + i * 4) * 4u, Vg + i * 4);
        }
        if (t < 128) {                               // mask: 32 rows x 4 quarters
            int r  = t >> 2;
            int cq = (t & 3) * 4;
            if (cq < nn) {
                int p = p0 + r; if (p >= P_) p = P_ - 1;   // clamp: no OOB read; value unused
                cpa16(db + (uint32_t)(MOFF + r * MST + cq) * 4u,
                      mask + ((size_t)b * P_ + p) * N_ + n0 + cq);
            }
        }
        asm volatile("cp.async.commit_group;" ::: "memory");
    };

    prefetch(0, 0);
    asm volatile("cp.async.wait_group 0;" ::: "memory");
    __syncthreads();

    float ma = -INFINITY, sa = 0.f;
    float mb = -INFINITY, sb = 0.f;
    float4 oa[4] = {}, ob[4] = {};

    int cur = 0;
    for (int n0 = 0; n0 < N_; n0 += ACH) {
        int nn = min(ACH, N_ - n0);                  // tail: 1000 = 62*16 + 8
        int nxt = cur ^ 1;
        if (n0 + ACH < N_) prefetch(n0 + ACH, nxt);  // overlap with compute below

        const float* k_sm = sm + cur * BUFF;
        const float* v_sm = k_sm + VOFF;
        const float* m_sm = k_sm + MOFF;

        float sca[ACH], scb[ACH];
        float cma = -INFINITY, cmb = -INFINITY;
#pragma unroll
        for (int j = 0; j < ACH; j++) {
            const float4* kp = (const float4*)(k_sm + j * HD_ + h * D_);
            float4 k0v = kp[0], k1v = kp[1], k2v = kp[2], k3v = kp[3];
            float ca, cb;
            ca  = qa[0].x * k0v.x + qa[0].y * k0v.y + qa[0].z * k0v.z + qa[0].w * k0v.w;
            ca += qa[1].x * k1v.x + qa[1].y * k1v.y + qa[1].z * k1v.z + qa[1].w * k1v.w;
            ca += qa[2].x * k2v.x + qa[2].y * k2v.y + qa[2].z * k2v.z + qa[2].w * k2v.w;
            ca += qa[3].x * k3v.x + qa[3].y * k3v.y + qa[3].z * k3v.z + qa[3].w * k3v.w;
            cb  = qb[0].x * k0v.x + qb[0].y * k0v.y + qb[0].z * k0v.z + qb[0].w * k0v.w;
            cb += qb[1].x * k1v.x + qb[1].y * k1v.y + qb[1].z * k1v.z + qb[1].w * k1v.w;
            cb += qb[2].x * k2v.x + qb[2].y * k2v.y + qb[2].z * k2v.z + qb[2].w * k2v.w;
            cb += qb[3].x * k3v.x + qb[3].y * k3v.y + qb[3].z * k3v.z + qb[3].w * k3v.w;
            ca = ca * 0.25f + m_sm[pl * MST + j];
            cb = cb * 0.25f + m_sm[(pl + 16) * MST + j];
            sca[j] = (j < nn) ? ca : -INFINITY;
            scb[j] = (j < nn) ? cb : -INFINITY;
            cma = fmaxf(cma, sca[j]);
            cmb = fmaxf(cmb, scb[j]);
        }
        float mna = fmaxf(ma, cma), mnb = fmaxf(mb, cmb);
        float fa = __expf(ma - mna), fb = __expf(mb - mnb);
        sa *= fa; sb *= fb;
#pragma unroll
        for (int i = 0; i < 4; i++) {
            oa[i].x *= fa; oa[i].y *= fa; oa[i].z *= fa; oa[i].w *= fa;
            ob[i].x *= fb; ob[i].y *= fb; ob[i].z *= fb; ob[i].w *= fb;
        }
#pragma unroll
        for (int j = 0; j < ACH; j++) {
            float wa = __expf(sca[j] - mna);
            float wb = __expf(scb[j] - mnb);
            sa += wa; sb += wb;
            const float4* vp = (const float4*)(v_sm + j * HD_ + h * D_);
            float4 v0 = vp[0], v1 = vp[1], v2 = vp[2], v3 = vp[3];
            oa[0].x += wa * v0.x; oa[0].y += wa * v0.y; oa[0].z += wa * v0.z; oa[0].w += wa * v0.w;
            oa[1].x += wa * v1.x; oa[1].y += wa * v1.y; oa[1].z += wa * v1.z; oa[1].w += wa * v1.w;
            oa[2].x += wa * v2.x; oa[2].y += wa * v2.y; oa[2].z += wa * v2.z; oa[2].w += wa * v2.w;
            oa[3].x += wa * v3.x; oa[3].y += wa * v3.y; oa[3].z += wa * v3.z; oa[3].w += wa * v3.w;
            ob[0].x += wb * v0.x; ob[0].y += wb * v0.y; ob[0].z += wb * v0.z; ob[0].w += wb * v0.w;
            ob[1].x += wb * v1.x; ob[1].y += wb * v1.y; ob[1].z += wb * v1.z; ob[1].w += wb * v1.w;
            ob[2].x += wb * v2.x; ob[2].y += wb * v2.y; ob[2].z += wb * v2.z; ob[2].w += wb * v2.w;
            ob[3].x += wb * v3.x; ob[3].y += wb * v3.y; ob[3].z += wb * v3.z; ob[3].w += wb * v3.w;
        }
        ma = mna; mb = mnb;

        asm volatile("cp.async.wait_group 0;" ::: "memory");
        __syncthreads();
        cur = nxt;
    }

    if (va) {
        float inv = 1.f / sa;
        float4* op = (float4*)(OC + ((size_t)b * P_ + pa) * HD_ + h * D_);
#pragma unroll
        for (int i = 0; i < 4; i++) {
            float4 o = oa[i];
            o.x *= inv; o.y *= inv; o.z *= inv; o.w *= inv;
            op[i] = o;
        }
    }
    if (vb) {
        float inv = 1.f / sb;
        float4* op = (float4*)(OC + ((size_t)b * P_ + pb) * HD_ + h * D_);
#pragma unroll
        for (int i = 0; i < 4; i++) {
            float4 o = ob[i];
            o.x *= inv; o.y *= inv; o.z *= inv; o.w *= inv;
            op[i] = o;
        }
    }
}

// ---------------- row softmax over S: one block per row ----------------
__global__ void __launch_bounds__(256)
softmax_k(const float* __restrict__ S, float* __restrict__ out)
{
    __shared__ float red[8];
    size_t row = blockIdx.x;
    const float* src = S   + row * N_;
    float*       dst = out + row * N_;
    int t = threadIdx.x;
    int lane = t & 31, w = t >> 5;

    float v[4];
    float lm = -INFINITY;
#pragma unroll
    for (int i = 0; i < 4; i++) {
        int n = t + i * 256;
        v[i] = (n < N_) ? src[n] : -INFINITY;
        lm = fmaxf(lm, v[i]);
    }
#pragma unroll
    for (int o = 16; o; o >>= 1) lm = fmaxf(lm, __shfl_xor_sync(~0u, lm, o));
    if (lane == 0) red[w] = lm;
    __syncthreads();
    lm = red[lane & 7];
#pragma unroll
    for (int o = 4; o; o >>= 1) lm = fmaxf(lm, __shfl_xor_sync(~0u, lm, o));
    float M = lm;

    float ls = 0.f;
#pragma unroll
    for (int i = 0; i < 4; i++) {
        v[i] = __expf(v[i] - M);
        ls += v[i];
    }
#pragma unroll
    for (int o = 16; o; o >>= 1) ls += __shfl_xor_sync(~0u, ls, o);
    __syncthreads();
    if (lane == 0) red[w] = ls;
    __syncthreads();
    ls = red[lane & 7];
#pragma unroll
    for (int o = 4; o; o >>= 1) ls += __shfl_xor_sync(~0u, ls, o);
    float inv = 1.f / ls;

#pragma unroll
    for (int i = 0; i < 4; i++) {
        int n = t + i * 256;
        if (n < N_) dst[n] = v[i] * inv;
    }
}

// ---------------- launch ----------------
static const int ATTN_SMEM = 2 * BUFF * (int)sizeof(float);   // ~69 KB

extern "C" void kernel_launch(void* const* d_in, const int* in_sizes, int n_in,
                              void* d_out, int out_size)
{
    const float* eln  = (const float*)d_in[0];
    const float* attr = (const float*)d_in[1];
    const float* mask = (const float*)d_in[2];
    const float* enc  = (const float*)d_in[3];
    const float* Wq   = (const float*)d_in[4];  // [257, 256]
    const float* Wk   = (const float*)d_in[5];
    const float* Wv   = (const float*)d_in[6];
    const float* Wc   = (const float*)d_in[7];
    const float* bc   = (const float*)d_in[8];
    float* out = (float*)d_out;

    float *Kp, *Vp, *Qp, *OCp, *MHp, *Sp;
    cudaGetSymbolAddress((void**)&Kp,  g_K);
    cudaGetSymbolAddress((void**)&Vp,  g_V);
    cudaGetSymbolAddress((void**)&Qp,  g_Q);
    cudaGetSymbolAddress((void**)&OCp, g_OC);
    cudaGetSymbolAddress((void**)&MHp, g_MH);
    cudaGetSymbolAddress((void**)&Sp,  g_S);

    cudaFuncSetAttribute(attn_k, cudaFuncAttributeMaxDynamicSharedMemorySize, ATTN_SMEM);

    dim3 gg(HD_ / GN, (B_ * N_) / GM);   // (4, 125)

    gemm2<<<gg, 256>>>(enc, Wk, Kp, HD_, nullptr, nullptr, nullptr);
    gemm2<<<gg, 256>>>(enc, Wv, Vp, HD_, nullptr, nullptr, nullptr);
    gemm2<<<gg, 256>>>(eln, Wq, Qp, HD_, nullptr, attr, Wq + 256 * 256);

    attn_k<<<dim3((P_ + 31) / 32, B_), 256, ATTN_SMEM>>>(Qp, Kp, Vp, mask, OCp);

    gemm2<<<gg, 256>>>(OCp, Wc, MHp, E_, bc, nullptr, nullptr);

    dim3 gp((N_ + GN - 1) / GN, (P_ + GM - 1) / GM, B_);   // (16, 8, 16)
    abT2     <<<gp, 256>>>(MHp, enc, mask, Sp);
    softmax_k<<<B_ * P_, 256>>>(Sp, out);
}